// round 15
// baseline (speedup 1.0000x reference)
#include <cuda_runtime.h>
#include <cuda_fp16.h>
#include <cstdint>

// ---------------------------------------------------------------------------
// MLA forward. fp16 mma.sync m16n8k16 (fp32 accum), 3-stage cp.async,
// ldmatrix.x4 fragment loads, all GEMMs in TRANSB ([N][K]) layout
// (V transposed once so attn@V also qualifies).
//   B=2, S=2048, D=2048, H=16, DH=128, DL=512
// ---------------------------------------------------------------------------

#define BDIM 2
#define SEQ 2048
#define DMODEL 2048
#define NHEAD 16
#define DHEAD 128
#define DLAT 512
#define ROWS (BDIM * SEQ)          // 4096

// fp16 intermediates
__device__ __half g_xh[(size_t)ROWS * DMODEL];
__device__ __half g_z[(size_t)ROWS * DLAT];
__device__ __half g_q[(size_t)ROWS * DMODEL];
__device__ __half g_k[(size_t)NHEAD * ROWS * DHEAD];
__device__ __half g_v[(size_t)NHEAD * ROWS * DHEAD];
__device__ __half g_vt[(size_t)NHEAD * BDIM * DHEAD * SEQ];    // V^T per (h,b)
__device__ __half g_scores[(size_t)BDIM * NHEAD * SEQ * SEQ];  // 256 MB
__device__ __half g_ao[(size_t)ROWS * DMODEL];

// fp16 transposed weights [N][K]
__device__ __half g_wlat_t[(size_t)DLAT * DMODEL];
__device__ __half g_wq_t[(size_t)DMODEL * DMODEL];
__device__ __half g_wk_t[(size_t)NHEAD * DHEAD * DLAT];
__device__ __half g_wv_t[(size_t)NHEAD * DHEAD * DLAT];
__device__ __half g_wo_t[(size_t)DMODEL * DMODEL];

#define BM 128
#define BN 128
#define BKT 32                      // halves per K-chunk (2 x k16 steps)
#define STAGES 3
#define ASTR 40                     // BKT + 8 halves (LDSM conflict-free)

#define SMEM_G (STAGES * (BM + BN) * ASTR * 2)   // 61440 B

// ---------------- helpers ----------------

__device__ __forceinline__ void cp_async16(void* smem_dst, const void* gmem_src)
{
    uint32_t s = (uint32_t)__cvta_generic_to_shared(smem_dst);
    asm volatile("cp.async.cg.shared.global [%0], [%1], 16;\n" :: "r"(s), "l"(gmem_src));
}
__device__ __forceinline__ void cp_commit()
{
    asm volatile("cp.async.commit_group;\n");
}
template <int N>
__device__ __forceinline__ void cp_wait()
{
    asm volatile("cp.async.wait_group %0;\n" :: "n"(N));
}

#define LDSM4(r0, r1, r2, r3, addr)                                            \
    asm volatile("ldmatrix.sync.aligned.m8n8.x4.shared.b16 {%0,%1,%2,%3}, [%4];" \
        : "=r"(r0), "=r"(r1), "=r"(r2), "=r"(r3) : "r"(addr))

#define MMA_F16(acc, a0, a1, a2, a3, b0, b1)                                   \
    asm volatile(                                                              \
        "mma.sync.aligned.m16n8k16.row.col.f32.f16.f16.f32 "                   \
        "{%0,%1,%2,%3},{%4,%5,%6,%7},{%8,%9},{%0,%1,%2,%3};\n"                 \
        : "+f"((acc)[0]), "+f"((acc)[1]), "+f"((acc)[2]), "+f"((acc)[3])       \
        : "r"(a0), "r"(a1), "r"(a2), "r"(a3), "r"(b0), "r"(b1))

// ---------------- GEMM core (TRANSB only) ----------------
// C = alpha * A @ B^T (+bias).  A:[M,K] half lda.  B:[N,K] half ldb.
// C: OUTH ? half : float, ldc.
// 128x128 tile, 256 thr (8 warps 2x4), warp tile 64x32, m16n8k16, LDSM frags.
template <bool OUTH>
__device__ __forceinline__ void gemm_h(
    const __half* __restrict__ A, int lda,
    const __half* __restrict__ B, int ldb,
    const float* __restrict__ bias,
    void* __restrict__ Cp, int ldc,
    int K, float alpha)
{
    extern __shared__ __half smh[];
    __half* As = smh;                          // STAGES * BM * ASTR
    __half* Bs = smh + STAGES * BM * ASTR;     // STAGES * BN * ASTR

    const int tid = threadIdx.x;
    const int lane = tid & 31;
    const int wid = tid >> 5;
    const int wm = wid & 1;
    const int wn = wid >> 1;
    const int grp = lane >> 2;
    const int qid = lane & 3;

    const int m0 = blockIdx.y * BM;
    const int n0 = blockIdx.x * BN;

    // tile load: 128 rows x 4 chunks of 8 halves, 2 per thread per array
    auto issue = [&](int st, int k0) {
        __half* Ad = As + st * (BM * ASTR);
        __half* Bd = Bs + st * (BN * ASTR);
        #pragma unroll
        for (int p = 0; p < 2; p++) {
            const int id = tid + 256 * p;
            const int row = id >> 2, ch = id & 3;
            cp_async16(&Ad[row * ASTR + ch * 8],
                       &A[(size_t)(m0 + row) * lda + k0 + ch * 8]);
            cp_async16(&Bd[row * ASTR + ch * 8],
                       &B[(size_t)(n0 + row) * ldb + k0 + ch * 8]);
        }
        cp_commit();
    };

    float acc[4][4][4];
    #pragma unroll
    for (int mi = 0; mi < 4; mi++)
        #pragma unroll
        for (int ni = 0; ni < 4; ni++)
            #pragma unroll
            for (int r = 0; r < 4; r++) acc[mi][ni][r] = 0.0f;

    // per-lane ldmatrix base offsets (halves): row = lane&15, kcol = (lane>>4)*8
    const int lrow = lane & 15;
    const int lkof = (lane >> 4) * 8;

    auto compute = [&](int st) {
        const uint32_t abase = (uint32_t)__cvta_generic_to_shared(
            As + st * (BM * ASTR)) + (((wm * 64 + lrow) * ASTR + lkof) << 1);
        const uint32_t bbase = (uint32_t)__cvta_generic_to_shared(
            Bs + st * (BN * ASTR)) + (((wn * 32 + lrow) * ASTR + lkof) << 1);
        #pragma unroll
        for (int ks = 0; ks < BKT / 16; ks++) {
            uint32_t af[4][4];
            uint32_t bf[4][2];
            #pragma unroll
            for (int mi = 0; mi < 4; mi++)
                LDSM4(af[mi][0], af[mi][1], af[mi][2], af[mi][3],
                      abase + ((mi * 16 * ASTR + ks * 16) << 1));
            #pragma unroll
            for (int np = 0; np < 2; np++) {
                uint32_t r0, r1, r2, r3;
                LDSM4(r0, r1, r2, r3,
                      bbase + ((np * 16 * ASTR + ks * 16) << 1));
                bf[np * 2][0] = r0; bf[np * 2 + 1][0] = r1;
                bf[np * 2][1] = r2; bf[np * 2 + 1][1] = r3;
            }
            #pragma unroll
            for (int mi = 0; mi < 4; mi++)
                #pragma unroll
                for (int ni = 0; ni < 4; ni++)
                    MMA_F16(acc[mi][ni], af[mi][0], af[mi][1], af[mi][2],
                            af[mi][3], bf[ni][0], bf[ni][1]);
        }
    };

    const int nchunk = K / BKT;        // >= 4 for all call sites

    issue(0, 0);
    issue(1, BKT);

    int st = 0;
    for (int c = 0; c < nchunk; c++) {
        if (c == nchunk - 1) cp_wait<0>(); else cp_wait<1>();
        __syncthreads();
        if (c + 2 < nchunk) {
            int wst = st + 2; if (wst >= STAGES) wst -= STAGES;
            issue(wst, (c + 2) * BKT);
        }
        compute(st);
        if (++st == STAGES) st = 0;
    }

    // ---- epilogue ----
    const int row0 = m0 + wm * 64 + grp;
    const int col00 = n0 + wn * 32 + qid * 2;
    #pragma unroll
    for (int mi = 0; mi < 4; mi++) {
        #pragma unroll
        for (int ni = 0; ni < 4; ni++) {
            const int col = col00 + ni * 8;
            float bx = 0.0f, by = 0.0f;
            if (bias) { bx = bias[col]; by = bias[col + 1]; }
            const int r0 = row0 + mi * 16;
            float2 v0, v1;
            v0.x = acc[mi][ni][0] * alpha + bx;
            v0.y = acc[mi][ni][1] * alpha + by;
            v1.x = acc[mi][ni][2] * alpha + bx;
            v1.y = acc[mi][ni][3] * alpha + by;
            if (OUTH) {
                __half* Ch = (__half*)Cp;
                *reinterpret_cast<__half2*>(&Ch[(size_t)r0 * ldc + col]) =
                    __floats2half2_rn(v0.x, v0.y);
                *reinterpret_cast<__half2*>(&Ch[(size_t)(r0 + 8) * ldc + col]) =
                    __floats2half2_rn(v1.x, v1.y);
            } else {
                float* Cf = (float*)Cp;
                *reinterpret_cast<float2*>(&Cf[(size_t)r0 * ldc + col]) = v0;
                *reinterpret_cast<float2*>(&Cf[(size_t)(r0 + 8) * ldc + col]) = v1;
            }
        }
    }
}

// ---------------- conversion / transpose pre-passes ----------------

__global__ __launch_bounds__(256)
void k_cvt_h(const float* __restrict__ in, __half* __restrict__ out, int n4)
{
    const int i = blockIdx.x * 256 + threadIdx.x;
    if (i < n4) {
        float4 v = reinterpret_cast<const float4*>(in)[i];
        reinterpret_cast<__half2*>(out)[i * 2]     = __floats2half2_rn(v.x, v.y);
        reinterpret_cast<__half2*>(out)[i * 2 + 1] = __floats2half2_rn(v.z, v.w);
    }
}

// fp32 [R][C] -> fp16 [C][R] (per blockIdx.z slice)
__global__ __launch_bounds__(256)
void k_tr(const float* __restrict__ in, __half* __restrict__ out, int R, int C)
{
    __shared__ __half t[32][33];
    const float* src = in + (size_t)blockIdx.z * R * C;
    __half* dst = out + (size_t)blockIdx.z * R * C;
    const int x = blockIdx.x * 32 + threadIdx.x;
    const int y0 = blockIdx.y * 32 + threadIdx.y;
    #pragma unroll
    for (int i = 0; i < 32; i += 8) {
        const int y = y0 + i;
        if (y < R && x < C)
            t[threadIdx.y + i][threadIdx.x] = __float2half_rn(src[(size_t)y * C + x]);
    }
    __syncthreads();
    const int ox = blockIdx.y * 32 + threadIdx.x;
    const int oy0 = blockIdx.x * 32 + threadIdx.y;
    #pragma unroll
    for (int i = 0; i < 32; i += 8) {
        const int oy = oy0 + i;
        if (oy < C && ox < R)
            dst[(size_t)oy * R + ox] = t[threadIdx.x][threadIdx.y + i];
    }
}

// V [SEQ][DHEAD] fp16 -> V^T [DHEAD][SEQ] fp16 per (h,b) slice
__global__ __launch_bounds__(256)
void k_trv()
{
    __shared__ __half t[32][33];
    const int slice = blockIdx.z;          // h * BDIM + b
    const int h = slice >> 1;
    const int b = slice & 1;
    const __half* src = g_v + ((size_t)h * ROWS + (size_t)b * SEQ) * DHEAD;
    __half* dst = g_vt + (size_t)slice * DHEAD * SEQ;
    const int x = blockIdx.x * 32 + threadIdx.x;       // dhead
    const int y0 = blockIdx.y * 32 + threadIdx.y;      // seq
    #pragma unroll
    for (int i = 0; i < 32; i += 8)
        t[threadIdx.y + i][threadIdx.x] = src[(size_t)(y0 + i) * DHEAD + x];
    __syncthreads();
    const int ox = blockIdx.y * 32 + threadIdx.x;      // seq
    const int oy0 = blockIdx.x * 32 + threadIdx.y;     // dhead
    #pragma unroll
    for (int i = 0; i < 32; i += 8)
        dst[(size_t)(oy0 + i) * SEQ + ox] = t[threadIdx.x][threadIdx.y + i];
}

// ---------------- GEMM wrappers ----------------

__global__ __launch_bounds__(256, 2)
void k_proj_z(const float* __restrict__ b)
{
    gemm_h<true>(g_xh, DMODEL, g_wlat_t, DMODEL, b, g_z, DLAT, DMODEL, 1.0f);
}

__global__ __launch_bounds__(256, 2)
void k_proj_q(const float* __restrict__ b)
{
    gemm_h<true>(g_xh, DMODEL, g_wq_t, DMODEL, b, g_q, DMODEL, DMODEL, 1.0f);
}

__global__ __launch_bounds__(256, 2)
void k_proj_kv(const float* __restrict__ bk, const float* __restrict__ bv)
{
    const int zb = blockIdx.z;
    const int h = zb & (NHEAD - 1);
    const bool isv = zb >= NHEAD;
    const __half* w = (isv ? g_wv_t : g_wk_t) + (size_t)h * DLAT * DHEAD;
    const float* bb = (isv ? bv : bk) + (size_t)h * DHEAD;
    __half* C = (isv ? g_v : g_k) + (size_t)h * ROWS * DHEAD;
    gemm_h<true>(g_z, DLAT, w, DLAT, bb, C, DHEAD, DLAT, 1.0f);
}

__global__ __launch_bounds__(256, 2)
void k_scores()
{
    const int zb = blockIdx.z;
    const int b = zb >> 4;
    const int h = zb & (NHEAD - 1);
    const __half* A = g_q + (size_t)b * SEQ * DMODEL + (size_t)h * DHEAD;
    const __half* Bm = g_k + (size_t)h * ROWS * DHEAD + (size_t)b * SEQ * DHEAD;
    __half* C = g_scores + (size_t)zb * SEQ * SEQ;
    gemm_h<true>(A, DMODEL, Bm, DHEAD, nullptr, C, SEQ, DHEAD,
                 0.08838834764831845f /* 1/sqrt(128) */);
}

__global__ __launch_bounds__(256, 2)
void k_attn_v()
{
    const int zb = blockIdx.z;
    const int b = zb >> 4;
    const int h = zb & (NHEAD - 1);
    const __half* A = g_scores + (size_t)zb * SEQ * SEQ;
    const __half* Bm = g_vt + (size_t)(h * BDIM + b) * DHEAD * SEQ;  // [DH][SEQ]
    __half* C = g_ao + (size_t)b * SEQ * DMODEL + (size_t)h * DHEAD;
    gemm_h<true>(A, SEQ, Bm, SEQ, nullptr, C, DMODEL, SEQ, 1.0f);
}

__global__ __launch_bounds__(256, 2)
void k_proj_out(const float* __restrict__ b, float* __restrict__ out)
{
    gemm_h<false>(g_ao, DMODEL, g_wo_t, DMODEL, b, out, DMODEL, DMODEL, 1.0f);
}

// ---------------- softmax on fp16 scores ----------------
__global__ __launch_bounds__(256)
void k_softmax()
{
    __shared__ float red[9];
    const size_t row = blockIdx.x;
    __half* p = g_scores + row * (size_t)SEQ;
    const int t = threadIdx.x;

    __half2* pv = reinterpret_cast<__half2*>(p) + t * 4;
    float2 f[4];
    #pragma unroll
    for (int i = 0; i < 4; i++) f[i] = __half22float2(pv[i]);

    float m = -3.4e38f;
    #pragma unroll
    for (int i = 0; i < 4; i++) m = fmaxf(m, fmaxf(f[i].x, f[i].y));
    #pragma unroll
    for (int o = 16; o; o >>= 1) m = fmaxf(m, __shfl_xor_sync(0xffffffffu, m, o));
    if ((t & 31) == 0) red[t >> 5] = m;
    __syncthreads();
    if (t < 32) {
        float v = (t < 8) ? red[t] : -3.4e38f;
        #pragma unroll
        for (int o = 4; o; o >>= 1) v = fmaxf(v, __shfl_xor_sync(0xffffffffu, v, o));
        if (t == 0) red[8] = v;
    }
    __syncthreads();
    m = red[8];

    float s = 0.0f;
    #pragma unroll
    for (int i = 0; i < 4; i++) {
        f[i].x = __expf(f[i].x - m);
        f[i].y = __expf(f[i].y - m);
        s += f[i].x + f[i].y;
    }
    #pragma unroll
    for (int o = 16; o; o >>= 1) s += __shfl_xor_sync(0xffffffffu, s, o);
    __syncthreads();
    if ((t & 31) == 0) red[t >> 5] = s;
    __syncthreads();
    if (t < 32) {
        float v = (t < 8) ? red[t] : 0.0f;
        #pragma unroll
        for (int o = 4; o; o >>= 1) v += __shfl_xor_sync(0xffffffffu, v, o);
        if (t == 0) red[8] = v;
    }
    __syncthreads();
    const float inv = 1.0f / red[8];

    #pragma unroll
    for (int i = 0; i < 4; i++)
        pv[i] = __floats2half2_rn(f[i].x * inv, f[i].y * inv);
}

// ---------------- launch ----------------

extern "C" void kernel_launch(void* const* d_in, const int* in_sizes, int n_in,
                              void* d_out, int out_size)
{
    const float* x        = (const float*)d_in[0];
    const float* w_latent = (const float*)d_in[1];
    const float* b_latent = (const float*)d_in[2];
    const float* w_q      = (const float*)d_in[3];
    const float* b_q      = (const float*)d_in[4];
    const float* w_k      = (const float*)d_in[5];
    const float* b_k      = (const float*)d_in[6];
    const float* w_v      = (const float*)d_in[7];
    const float* b_v      = (const float*)d_in[8];
    const float* w_o      = (const float*)d_in[9];
    const float* b_o      = (const float*)d_in[10];
    float* out            = (float*)d_out;

    dim3 blk(256);
    dim3 tblk(32, 8);

    cudaFuncSetAttribute(k_proj_z,   cudaFuncAttributeMaxDynamicSharedMemorySize, SMEM_G);
    cudaFuncSetAttribute(k_proj_q,   cudaFuncAttributeMaxDynamicSharedMemorySize, SMEM_G);
    cudaFuncSetAttribute(k_proj_kv,  cudaFuncAttributeMaxDynamicSharedMemorySize, SMEM_G);
    cudaFuncSetAttribute(k_scores,   cudaFuncAttributeMaxDynamicSharedMemorySize, SMEM_G);
    cudaFuncSetAttribute(k_attn_v,   cudaFuncAttributeMaxDynamicSharedMemorySize, SMEM_G);
    cudaFuncSetAttribute(k_proj_out, cudaFuncAttributeMaxDynamicSharedMemorySize, SMEM_G);

    __half *p_xh, *p_wlat, *p_wq, *p_wk, *p_wv, *p_wo;
    cudaGetSymbolAddress((void**)&p_xh,   g_xh);
    cudaGetSymbolAddress((void**)&p_wlat, g_wlat_t);
    cudaGetSymbolAddress((void**)&p_wq,   g_wq_t);
    cudaGetSymbolAddress((void**)&p_wk,   g_wk_t);
    cudaGetSymbolAddress((void**)&p_wv,   g_wv_t);
    cudaGetSymbolAddress((void**)&p_wo,   g_wo_t);

    {
        const int n4 = (int)((size_t)ROWS * DMODEL / 4);
        k_cvt_h<<<(n4 + 255) / 256, blk>>>(x, p_xh, n4);
    }
    k_tr<<<dim3(DLAT / 32, DMODEL / 32), tblk>>>(w_latent, p_wlat, DMODEL, DLAT);
    k_tr<<<dim3(DMODEL / 32, DMODEL / 32), tblk>>>(w_q, p_wq, DMODEL, DMODEL);
    k_tr<<<dim3(DHEAD / 32, DLAT / 32, NHEAD), tblk>>>(w_k, p_wk, DLAT, DHEAD);
    k_tr<<<dim3(DHEAD / 32, DLAT / 32, NHEAD), tblk>>>(w_v, p_wv, DLAT, DHEAD);
    k_tr<<<dim3(DMODEL / 32, DMODEL / 32), tblk>>>(w_o, p_wo, DMODEL, DMODEL);

    k_proj_z<<<dim3(DLAT / BN, ROWS / BM), blk, SMEM_G>>>(b_latent);
    k_proj_q<<<dim3(DMODEL / BN, ROWS / BM), blk, SMEM_G>>>(b_q);
    k_proj_kv<<<dim3(DHEAD / BN, ROWS / BM, 2 * NHEAD), blk, SMEM_G>>>(b_k, b_v);
    k_trv<<<dim3(DHEAD / 32, SEQ / 32, NHEAD * BDIM), tblk>>>();
    k_scores<<<dim3(SEQ / BN, SEQ / BM, BDIM * NHEAD), blk, SMEM_G>>>();
    k_softmax<<<dim3(BDIM * NHEAD * SEQ), blk>>>();
    k_attn_v<<<dim3(DHEAD / BN, SEQ / BM, BDIM * NHEAD), blk, SMEM_G>>>();
    k_proj_out<<<dim3(DMODEL / BN, ROWS / BM), blk, SMEM_G>>>(b_o, out);
}

// round 16
// speedup vs baseline: 1.1141x; 1.1141x over previous
#include <cuda_runtime.h>
#include <cuda_fp16.h>
#include <cstdint>

// ---------------------------------------------------------------------------
// MLA forward. fp16 mma.sync m16n8k16 (fp32 accum).
// - General GEMMs: 3-stage cp.async, BKT=64 (one __syncthreads / 64-deep chunk)
// - k_scores (K=128): single-stage whole-K kernel (no pipeline, 1 barrier)
//   B=2, S=2048, D=2048, H=16, DH=128, DL=512
// ---------------------------------------------------------------------------

#define BDIM 2
#define SEQ 2048
#define DMODEL 2048
#define NHEAD 16
#define DHEAD 128
#define DLAT 512
#define ROWS (BDIM * SEQ)          // 4096

// fp16 intermediates
__device__ __half g_xh[(size_t)ROWS * DMODEL];
__device__ __half g_z[(size_t)ROWS * DLAT];
__device__ __half g_q[(size_t)ROWS * DMODEL];
__device__ __half g_k[(size_t)NHEAD * ROWS * DHEAD];
__device__ __half g_v[(size_t)NHEAD * ROWS * DHEAD];
__device__ __half g_scores[(size_t)BDIM * NHEAD * SEQ * SEQ];  // 256 MB
__device__ __half g_ao[(size_t)ROWS * DMODEL];

// fp16 transposed weights [N][K]
__device__ __half g_wlat_t[(size_t)DLAT * DMODEL];
__device__ __half g_wq_t[(size_t)DMODEL * DMODEL];
__device__ __half g_wk_t[(size_t)NHEAD * DHEAD * DLAT];
__device__ __half g_wv_t[(size_t)NHEAD * DHEAD * DLAT];
__device__ __half g_wo_t[(size_t)DMODEL * DMODEL];

#define BM 128
#define BN 128
#define BKT 64                      // halves per K-chunk (4 x k16 steps)
#define STAGES 3
#define ASTR 72                     // BKT + 8 halves (conflict-free)
#define BSTR_NN 136                 // BN + 8 halves

// dynamic smem bytes
#define SMEM_T3 (STAGES * (BM + BN) * ASTR * 2)                  // 110592
#define SMEM_N3 (STAGES * (BM * ASTR + BKT * BSTR_NN) * 2)       // 107520
#define ASTR_S 136                  // 128 + 8 (scores kernel, whole K)
#define SMEM_S  ((BM + BN) * ASTR_S * 2)                         // 69632

// ---------------- helpers ----------------

__device__ __forceinline__ void cp_async16(void* smem_dst, const void* gmem_src)
{
    uint32_t s = (uint32_t)__cvta_generic_to_shared(smem_dst);
    asm volatile("cp.async.cg.shared.global [%0], [%1], 16;\n" :: "r"(s), "l"(gmem_src));
}
__device__ __forceinline__ void cp_commit()
{
    asm volatile("cp.async.commit_group;\n");
}
template <int N>
__device__ __forceinline__ void cp_wait()
{
    asm volatile("cp.async.wait_group %0;\n" :: "n"(N));
}

__device__ __forceinline__ uint32_t packh(__half lo, __half hi)
{
    return (uint32_t)__half_as_ushort(lo) | ((uint32_t)__half_as_ushort(hi) << 16);
}

#define MMA_F16(acc, a0, a1, a2, a3, b0, b1)                                   \
    asm volatile(                                                              \
        "mma.sync.aligned.m16n8k16.row.col.f32.f16.f16.f32 "                   \
        "{%0,%1,%2,%3},{%4,%5,%6,%7},{%8,%9},{%0,%1,%2,%3};\n"                 \
        : "+f"((acc)[0]), "+f"((acc)[1]), "+f"((acc)[2]), "+f"((acc)[3])       \
        : "r"(a0), "r"(a1), "r"(a2), "r"(a3), "r"(b0), "r"(b1))

// ---------------- epilogue (shared) ----------------
template <bool OUTH>
__device__ __forceinline__ void gemm_epilogue(
    float acc[4][4][4], const float* bias, void* Cp, int ldc,
    int m0, int n0, int wm, int wn, int grp, int qid, float alpha)
{
    const int row0 = m0 + wm * 64 + grp;
    const int col00 = n0 + wn * 32 + qid * 2;
    #pragma unroll
    for (int mi = 0; mi < 4; mi++) {
        #pragma unroll
        for (int ni = 0; ni < 4; ni++) {
            const int col = col00 + ni * 8;
            float bx = 0.0f, by = 0.0f;
            if (bias) { bx = bias[col]; by = bias[col + 1]; }
            const int r0 = row0 + mi * 16;
            float2 v0, v1;
            v0.x = acc[mi][ni][0] * alpha + bx;
            v0.y = acc[mi][ni][1] * alpha + by;
            v1.x = acc[mi][ni][2] * alpha + bx;
            v1.y = acc[mi][ni][3] * alpha + by;
            if (OUTH) {
                __half* Ch = (__half*)Cp;
                *reinterpret_cast<__half2*>(&Ch[(size_t)r0 * ldc + col]) =
                    __floats2half2_rn(v0.x, v0.y);
                *reinterpret_cast<__half2*>(&Ch[(size_t)(r0 + 8) * ldc + col]) =
                    __floats2half2_rn(v1.x, v1.y);
            } else {
                float* Cf = (float*)Cp;
                *reinterpret_cast<float2*>(&Cf[(size_t)r0 * ldc + col]) = v0;
                *reinterpret_cast<float2*>(&Cf[(size_t)(r0 + 8) * ldc + col]) = v1;
            }
        }
    }
}

// ---------------- GEMM core (3-stage, BKT=64) ----------------
// C = alpha * A @ B (+bias).  A:[M,K] half lda.
// B: TRANSB ? [N,K] : [K,N], half ldb.  C: OUTH ? half : float.
// 128x128 tile, 256 thr (8 warps 2x4), warp tile 64x32, fp16 m16n8k16.
template <bool TRANSB, bool OUTH>
__device__ __forceinline__ void gemm_h(
    const __half* __restrict__ A, int lda,
    const __half* __restrict__ B, int ldb,
    const float* __restrict__ bias,
    void* __restrict__ Cp, int ldc,
    int K, float alpha)
{
    constexpr int BS_SZ = TRANSB ? (BN * ASTR) : (BKT * BSTR_NN);

    extern __shared__ __half smh[];
    __half* As = smh;                          // STAGES * BM * ASTR
    __half* Bs = smh + STAGES * BM * ASTR;     // STAGES * BS_SZ

    const int tid = threadIdx.x;
    const int lane = tid & 31;
    const int wid = tid >> 5;
    const int wm = wid & 1;
    const int wn = wid >> 1;
    const int grp = lane >> 2;
    const int qid = lane & 3;

    const int m0 = blockIdx.y * BM;
    const int n0 = blockIdx.x * BN;

    // per chunk: A 128x64 halves = 1024 x 16B chunks (4/thread); B same count
    auto issue = [&](int st, int k0) {
        __half* Ad = As + st * (BM * ASTR);
        __half* Bd = Bs + st * BS_SZ;
        #pragma unroll
        for (int p = 0; p < 4; p++) {
            const int id = tid + 256 * p;
            const int row = id >> 3, ch = id & 7;        // 8 chunks of 8 halves
            cp_async16(&Ad[row * ASTR + ch * 8],
                       &A[(size_t)(m0 + row) * lda + k0 + ch * 8]);
            if (TRANSB) {
                cp_async16(&Bd[row * ASTR + ch * 8],
                           &B[(size_t)(n0 + row) * ldb + k0 + ch * 8]);
            } else {
                const int brow = id >> 4, bch = id & 15; // 64 rows x 16 chunks
                cp_async16(&Bd[brow * BSTR_NN + bch * 8],
                           &B[(size_t)(k0 + brow) * ldb + n0 + bch * 8]);
            }
        }
        cp_commit();
    };

    float acc[4][4][4];
    #pragma unroll
    for (int mi = 0; mi < 4; mi++)
        #pragma unroll
        for (int ni = 0; ni < 4; ni++)
            #pragma unroll
            for (int r = 0; r < 4; r++) acc[mi][ni][r] = 0.0f;

    auto compute = [&](int st) {
        const __half* Ad = As + st * (BM * ASTR);
        const __half* Bd = Bs + st * BS_SZ;
        #pragma unroll
        for (int ks = 0; ks < BKT / 16; ks++) {
            uint32_t af[4][4];
            uint32_t bf[4][2];
            const int kc = ks * 16 + qid * 2;
            #pragma unroll
            for (int mi = 0; mi < 4; mi++) {
                const int r = wm * 64 + mi * 16 + grp;
                af[mi][0] = *reinterpret_cast<const uint32_t*>(&Ad[(r) * ASTR + kc]);
                af[mi][1] = *reinterpret_cast<const uint32_t*>(&Ad[(r + 8) * ASTR + kc]);
                af[mi][2] = *reinterpret_cast<const uint32_t*>(&Ad[(r) * ASTR + kc + 8]);
                af[mi][3] = *reinterpret_cast<const uint32_t*>(&Ad[(r + 8) * ASTR + kc + 8]);
            }
            #pragma unroll
            for (int ni = 0; ni < 4; ni++) {
                const int n = wn * 32 + ni * 8 + grp;
                if (TRANSB) {
                    bf[ni][0] = *reinterpret_cast<const uint32_t*>(&Bd[n * ASTR + kc]);
                    bf[ni][1] = *reinterpret_cast<const uint32_t*>(&Bd[n * ASTR + kc + 8]);
                } else {
                    bf[ni][0] = packh(Bd[(kc) * BSTR_NN + n], Bd[(kc + 1) * BSTR_NN + n]);
                    bf[ni][1] = packh(Bd[(kc + 8) * BSTR_NN + n], Bd[(kc + 9) * BSTR_NN + n]);
                }
            }
            #pragma unroll
            for (int mi = 0; mi < 4; mi++)
                #pragma unroll
                for (int ni = 0; ni < 4; ni++)
                    MMA_F16(acc[mi][ni], af[mi][0], af[mi][1], af[mi][2],
                            af[mi][3], bf[ni][0], bf[ni][1]);
        }
    };

    const int nchunk = K / BKT;        // >= 8 for all call sites

    issue(0, 0);
    issue(1, BKT);

    int st = 0;
    for (int c = 0; c < nchunk; c++) {
        if (c == nchunk - 1) cp_wait<0>(); else cp_wait<1>();
        __syncthreads();
        if (c + 2 < nchunk) {
            int wst = st + 2; if (wst >= STAGES) wst -= STAGES;
            issue(wst, (c + 2) * BKT);
        }
        compute(st);
        if (++st == STAGES) st = 0;
    }

    gemm_epilogue<OUTH>(acc, bias, Cp, ldc, m0, n0, wm, wn, grp, qid, alpha);
}

// ---------------- scores kernel: K=128 fully resident ----------------
// C[SEQ,SEQ](half) = alpha * Q_slice @ K_slice^T. One load batch, one sync.
__global__ __launch_bounds__(256, 2)
void k_scores()
{
    extern __shared__ __half smh[];
    __half* As = smh;                  // BM * ASTR_S
    __half* Bs = smh + BM * ASTR_S;    // BN * ASTR_S

    const int tid = threadIdx.x;
    const int lane = tid & 31;
    const int wid = tid >> 5;
    const int wm = wid & 1;
    const int wn = wid >> 1;
    const int grp = lane >> 2;
    const int qid = lane & 3;

    const int zb = blockIdx.z;
    const int b = zb >> 4;
    const int h = zb & (NHEAD - 1);
    const __half* A = g_q + (size_t)b * SEQ * DMODEL + (size_t)h * DHEAD;
    const __half* Bm = g_k + (size_t)h * ROWS * DHEAD + (size_t)b * SEQ * DHEAD;
    __half* C = g_scores + (size_t)zb * SEQ * SEQ;

    const int m0 = blockIdx.y * BM;
    const int n0 = blockIdx.x * BN;

    // whole-K load: 128 rows x 16 chunks of 8 halves = 2048 chunks -> 8/thread
    #pragma unroll
    for (int p = 0; p < 8; p++) {
        const int id = tid + 256 * p;
        const int row = id >> 4, ch = id & 15;
        cp_async16(&As[row * ASTR_S + ch * 8],
                   &A[(size_t)(m0 + row) * DMODEL + ch * 8]);
        cp_async16(&Bs[row * ASTR_S + ch * 8],
                   &Bm[(size_t)(n0 + row) * DHEAD + ch * 8]);
    }
    cp_commit();

    float acc[4][4][4];
    #pragma unroll
    for (int mi = 0; mi < 4; mi++)
        #pragma unroll
        for (int ni = 0; ni < 4; ni++)
            #pragma unroll
            for (int r = 0; r < 4; r++) acc[mi][ni][r] = 0.0f;

    cp_wait<0>();
    __syncthreads();

    #pragma unroll
    for (int ks = 0; ks < DHEAD / 16; ks++) {
        uint32_t af[4][4];
        uint32_t bf[4][2];
        const int kc = ks * 16 + qid * 2;
        #pragma unroll
        for (int mi = 0; mi < 4; mi++) {
            const int r = wm * 64 + mi * 16 + grp;
            af[mi][0] = *reinterpret_cast<const uint32_t*>(&As[(r) * ASTR_S + kc]);
            af[mi][1] = *reinterpret_cast<const uint32_t*>(&As[(r + 8) * ASTR_S + kc]);
            af[mi][2] = *reinterpret_cast<const uint32_t*>(&As[(r) * ASTR_S + kc + 8]);
            af[mi][3] = *reinterpret_cast<const uint32_t*>(&As[(r + 8) * ASTR_S + kc + 8]);
        }
        #pragma unroll
        for (int ni = 0; ni < 4; ni++) {
            const int n = wn * 32 + ni * 8 + grp;
            bf[ni][0] = *reinterpret_cast<const uint32_t*>(&Bs[n * ASTR_S + kc]);
            bf[ni][1] = *reinterpret_cast<const uint32_t*>(&Bs[n * ASTR_S + kc + 8]);
        }
        #pragma unroll
        for (int mi = 0; mi < 4; mi++)
            #pragma unroll
            for (int ni = 0; ni < 4; ni++)
                MMA_F16(acc[mi][ni], af[mi][0], af[mi][1], af[mi][2],
                        af[mi][3], bf[ni][0], bf[ni][1]);
    }

    gemm_epilogue<true>(acc, nullptr, C, SEQ, m0, n0, wm, wn, grp, qid,
                        0.08838834764831845f /* 1/sqrt(128) */);
}

// ---------------- conversion / transpose pre-passes ----------------

__global__ __launch_bounds__(256)
void k_cvt_h(const float* __restrict__ in, __half* __restrict__ out, int n4)
{
    const int i = blockIdx.x * 256 + threadIdx.x;
    if (i < n4) {
        float4 v = reinterpret_cast<const float4*>(in)[i];
        reinterpret_cast<__half2*>(out)[i * 2]     = __floats2half2_rn(v.x, v.y);
        reinterpret_cast<__half2*>(out)[i * 2 + 1] = __floats2half2_rn(v.z, v.w);
    }
}

// fp32 [R][C] -> fp16 [C][R] (per blockIdx.z slice)
__global__ __launch_bounds__(256)
void k_tr(const float* __restrict__ in, __half* __restrict__ out, int R, int C)
{
    __shared__ __half t[32][33];
    const float* src = in + (size_t)blockIdx.z * R * C;
    __half* dst = out + (size_t)blockIdx.z * R * C;
    const int x = blockIdx.x * 32 + threadIdx.x;
    const int y0 = blockIdx.y * 32 + threadIdx.y;
    #pragma unroll
    for (int i = 0; i < 32; i += 8) {
        const int y = y0 + i;
        if (y < R && x < C)
            t[threadIdx.y + i][threadIdx.x] = __float2half_rn(src[(size_t)y * C + x]);
    }
    __syncthreads();
    const int ox = blockIdx.y * 32 + threadIdx.x;
    const int oy0 = blockIdx.x * 32 + threadIdx.y;
    #pragma unroll
    for (int i = 0; i < 32; i += 8) {
        const int oy = oy0 + i;
        if (oy < C && ox < R)
            dst[(size_t)oy * R + ox] = t[threadIdx.x][threadIdx.y + i];
    }
}

// ---------------- GEMM wrappers ----------------

__global__ __launch_bounds__(256, 2)
void k_proj_z(const float* __restrict__ b)
{
    gemm_h<true, true>(g_xh, DMODEL, g_wlat_t, DMODEL, b, g_z, DLAT, DMODEL, 1.0f);
}

__global__ __launch_bounds__(256, 2)
void k_proj_q(const float* __restrict__ b)
{
    gemm_h<true, true>(g_xh, DMODEL, g_wq_t, DMODEL, b, g_q, DMODEL, DMODEL, 1.0f);
}

__global__ __launch_bounds__(256, 2)
void k_proj_kv(const float* __restrict__ bk, const float* __restrict__ bv)
{
    const int zb = blockIdx.z;
    const int h = zb & (NHEAD - 1);
    const bool isv = zb >= NHEAD;
    const __half* w = (isv ? g_wv_t : g_wk_t) + (size_t)h * DLAT * DHEAD;
    const float* bb = (isv ? bv : bk) + (size_t)h * DHEAD;
    __half* C = (isv ? g_v : g_k) + (size_t)h * ROWS * DHEAD;
    gemm_h<true, true>(g_z, DLAT, w, DLAT, bb, C, DHEAD, DLAT, 1.0f);
}

__global__ __launch_bounds__(256, 2)
void k_attn_v()
{
    const int zb = blockIdx.z;
    const int b = zb >> 4;
    const int h = zb & (NHEAD - 1);
    const __half* A = g_scores + (size_t)zb * SEQ * SEQ;
    const __half* Bm = g_v + (size_t)h * ROWS * DHEAD + (size_t)b * SEQ * DHEAD;
    __half* C = g_ao + (size_t)b * SEQ * DMODEL + (size_t)h * DHEAD;
    gemm_h<false, true>(A, SEQ, Bm, DHEAD, nullptr, C, DMODEL, SEQ, 1.0f);
}

__global__ __launch_bounds__(256, 2)
void k_proj_out(const float* __restrict__ b, float* __restrict__ out)
{
    gemm_h<true, false>(g_ao, DMODEL, g_wo_t, DMODEL, b, out, DMODEL, DMODEL, 1.0f);
}

// ---------------- softmax on fp16 scores ----------------
__global__ __launch_bounds__(256)
void k_softmax()
{
    __shared__ float red[9];
    const size_t row = blockIdx.x;
    __half* p = g_scores + row * (size_t)SEQ;
    const int t = threadIdx.x;

    __half2* pv = reinterpret_cast<__half2*>(p) + t * 4;
    float2 f[4];
    #pragma unroll
    for (int i = 0; i < 4; i++) f[i] = __half22float2(pv[i]);

    float m = -3.4e38f;
    #pragma unroll
    for (int i = 0; i < 4; i++) m = fmaxf(m, fmaxf(f[i].x, f[i].y));
    #pragma unroll
    for (int o = 16; o; o >>= 1) m = fmaxf(m, __shfl_xor_sync(0xffffffffu, m, o));
    if ((t & 31) == 0) red[t >> 5] = m;
    __syncthreads();
    if (t < 32) {
        float v = (t < 8) ? red[t] : -3.4e38f;
        #pragma unroll
        for (int o = 4; o; o >>= 1) v = fmaxf(v, __shfl_xor_sync(0xffffffffu, v, o));
        if (t == 0) red[8] = v;
    }
    __syncthreads();
    m = red[8];

    float s = 0.0f;
    #pragma unroll
    for (int i = 0; i < 4; i++) {
        f[i].x = __expf(f[i].x - m);
        f[i].y = __expf(f[i].y - m);
        s += f[i].x + f[i].y;
    }
    #pragma unroll
    for (int o = 16; o; o >>= 1) s += __shfl_xor_sync(0xffffffffu, s, o);
    __syncthreads();
    if ((t & 31) == 0) red[t >> 5] = s;
    __syncthreads();
    if (t < 32) {
        float v = (t < 8) ? red[t] : 0.0f;
        #pragma unroll
        for (int o = 4; o; o >>= 1) v += __shfl_xor_sync(0xffffffffu, v, o);
        if (t == 0) red[8] = v;
    }
    __syncthreads();
    const float inv = 1.0f / red[8];

    #pragma unroll
    for (int i = 0; i < 4; i++)
        pv[i] = __floats2half2_rn(f[i].x * inv, f[i].y * inv);
}

// ---------------- launch ----------------

extern "C" void kernel_launch(void* const* d_in, const int* in_sizes, int n_in,
                              void* d_out, int out_size)
{
    const float* x        = (const float*)d_in[0];
    const float* w_latent = (const float*)d_in[1];
    const float* b_latent = (const float*)d_in[2];
    const float* w_q      = (const float*)d_in[3];
    const float* b_q      = (const float*)d_in[4];
    const float* w_k      = (const float*)d_in[5];
    const float* b_k      = (const float*)d_in[6];
    const float* w_v      = (const float*)d_in[7];
    const float* b_v      = (const float*)d_in[8];
    const float* w_o      = (const float*)d_in[9];
    const float* b_o      = (const float*)d_in[10];
    float* out            = (float*)d_out;

    dim3 blk(256);
    dim3 tblk(32, 8);

    cudaFuncSetAttribute(k_proj_z,   cudaFuncAttributeMaxDynamicSharedMemorySize, SMEM_T3);
    cudaFuncSetAttribute(k_proj_q,   cudaFuncAttributeMaxDynamicSharedMemorySize, SMEM_T3);
    cudaFuncSetAttribute(k_proj_kv,  cudaFuncAttributeMaxDynamicSharedMemorySize, SMEM_T3);
    cudaFuncSetAttribute(k_scores,   cudaFuncAttributeMaxDynamicSharedMemorySize, SMEM_S);
    cudaFuncSetAttribute(k_attn_v,   cudaFuncAttributeMaxDynamicSharedMemorySize, SMEM_N3);
    cudaFuncSetAttribute(k_proj_out, cudaFuncAttributeMaxDynamicSharedMemorySize, SMEM_T3);

    __half *p_xh, *p_wlat, *p_wq, *p_wk, *p_wv, *p_wo;
    cudaGetSymbolAddress((void**)&p_xh,   g_xh);
    cudaGetSymbolAddress((void**)&p_wlat, g_wlat_t);
    cudaGetSymbolAddress((void**)&p_wq,   g_wq_t);
    cudaGetSymbolAddress((void**)&p_wk,   g_wk_t);
    cudaGetSymbolAddress((void**)&p_wv,   g_wv_t);
    cudaGetSymbolAddress((void**)&p_wo,   g_wo_t);

    {
        const int n4 = (int)((size_t)ROWS * DMODEL / 4);
        k_cvt_h<<<(n4 + 255) / 256, blk>>>(x, p_xh, n4);
    }
    k_tr<<<dim3(DLAT / 32, DMODEL / 32), tblk>>>(w_latent, p_wlat, DMODEL, DLAT);
    k_tr<<<dim3(DMODEL / 32, DMODEL / 32), tblk>>>(w_q, p_wq, DMODEL, DMODEL);
    k_tr<<<dim3(DHEAD / 32, DLAT / 32, NHEAD), tblk>>>(w_k, p_wk, DLAT, DHEAD);
    k_tr<<<dim3(DHEAD / 32, DLAT / 32, NHEAD), tblk>>>(w_v, p_wv, DLAT, DHEAD);
    k_tr<<<dim3(DMODEL / 32, DMODEL / 32), tblk>>>(w_o, p_wo, DMODEL, DMODEL);

    k_proj_z<<<dim3(DLAT / BN, ROWS / BM), blk, SMEM_T3>>>(b_latent);
    k_proj_q<<<dim3(DMODEL / BN, ROWS / BM), blk, SMEM_T3>>>(b_q);
    k_proj_kv<<<dim3(DHEAD / BN, ROWS / BM, 2 * NHEAD), blk, SMEM_T3>>>(b_k, b_v);
    k_scores<<<dim3(SEQ / BN, SEQ / BM, BDIM * NHEAD), blk, SMEM_S>>>();
    k_softmax<<<dim3(BDIM * NHEAD * SEQ), blk>>>();
    k_attn_v<<<dim3(DHEAD / BN, SEQ / BM, BDIM * NHEAD), blk, SMEM_N3>>>();
    k_proj_out<<<dim3(DMODEL / BN, ROWS / BM), blk, SMEM_T3>>>(b_o, out);
}